// round 1
// baseline (speedup 1.0000x reference)
#include <cuda_runtime.h>
#include <cuda_bf16.h>
#include <cstdint>

#define BATCH 128
#define SEQ   512
#define HID   1024
#define H2    2048
#define EMB   512
#define VOCAB 32000
#define KG    3584          /* 2048 ctx + 512 emb + 1024 h */
#define NG    4096
#define LDS_PAD 40          /* 32 + 8 bf16: 80B row stride -> conflict-free ldmatrix */

__device__ float g_rnn[BATCH * KG];     // [128][3584]: ctx | emb | h
__device__ float g_gates[BATCH * NG];   // [128][4096]

// ---------------------------------------------------------------------------
// prep: zero ctx region + gates, gather embedding, copy hidden into rnn_in
// ---------------------------------------------------------------------------
__global__ void prep_kernel(const int* __restrict__ x,
                            const float* __restrict__ emb_table,
                            const float* __restrict__ hidden)
{
    int b = blockIdx.x, t = threadIdx.x;
    float* r = g_rnn + b * KG;
    for (int j = t; j < H2; j += 256) r[j] = 0.f;
    int tok = x[b];
    for (int j = t; j < EMB; j += 256) r[H2 + j] = emb_table[(size_t)tok * EMB + j];
    for (int j = t; j < HID; j += 256) r[H2 + EMB + j] = hidden[b * HID + j];
    for (int j = t; j < NG; j += 256) g_gates[b * NG + j] = 0.f;
}

// ---------------------------------------------------------------------------
// attention: one pass over encoder_states with online softmax.
// 1 CTA per batch element; 8 warps; warp w handles s = w, w+8, ...
// Each warp keeps a full 2048-wide context accumulator in registers
// (64 floats/thread). Warps merge at the end via smem + global atomicAdd.
// ---------------------------------------------------------------------------
__global__ __launch_bounds__(256) void attn_kernel(
    const float* __restrict__ enc,
    const float* __restrict__ hidden,
    const float* __restrict__ W_e,
    const float* __restrict__ b_e)
{
    __shared__ float s_w2[H2];
    __shared__ float s_red[8];
    __shared__ float s_m[8], s_z[8];
    __shared__ float s_hb;

    int b = blockIdx.x, t = threadIdx.x;
    int warp = t >> 5, lane = t & 31;

    // stage w2 (attention weights over encoder features) in smem
    for (int j = t; j < H2; j += 256) s_w2[j] = W_e[HID + j];

    // hb = hidden[b] . W_e[0:HID] + b_e   (same for every s)
    float p = 0.f;
    for (int j = t; j < HID; j += 256) p += hidden[b * HID + j] * W_e[j];
    #pragma unroll
    for (int o = 16; o > 0; o >>= 1) p += __shfl_xor_sync(0xffffffffu, p, o);
    if (lane == 0) s_red[warp] = p;
    __syncthreads();
    if (t == 0) {
        float s = 0.f;
        for (int i = 0; i < 8; i++) s += s_red[i];
        s_hb = s + b_e[0];
    }
    __syncthreads();
    float hb = s_hb;

    float4 acc[16];
    #pragma unroll
    for (int i = 0; i < 16; i++) acc[i] = make_float4(0.f, 0.f, 0.f, 0.f);
    float m = -1e30f, Z = 0.f;
    const float4* w2v = (const float4*)s_w2;

    for (int s = warp; s < SEQ; s += 8) {
        const float4* row = (const float4*)(enc + ((size_t)s * BATCH + b) * H2);
        float4 v[16];
        float pr = 0.f;
        #pragma unroll
        for (int i = 0; i < 16; i++) {
            v[i] = row[lane + 32 * i];
            float4 w = w2v[lane + 32 * i];
            pr += v[i].x * w.x + v[i].y * w.y + v[i].z * w.z + v[i].w * w.w;
        }
        #pragma unroll
        for (int o = 16; o > 0; o >>= 1) pr += __shfl_xor_sync(0xffffffffu, pr, o);
        float e  = fmaxf(pr + hb, 0.f);      // relu
        float mn = fmaxf(m, e);
        float sc = __expf(m - mn);           // first iter: exp(-1e30)=0
        float wg = __expf(e - mn);
        Z = Z * sc + wg;
        #pragma unroll
        for (int i = 0; i < 16; i++) {
            acc[i].x = acc[i].x * sc + wg * v[i].x;
            acc[i].y = acc[i].y * sc + wg * v[i].y;
            acc[i].z = acc[i].z * sc + wg * v[i].z;
            acc[i].w = acc[i].w * sc + wg * v[i].w;
        }
        m = mn;
    }

    if (lane == 0) { s_m[warp] = m; s_z[warp] = Z; }
    __syncthreads();
    float M = -1e30f;
    #pragma unroll
    for (int i = 0; i < 8; i++) M = fmaxf(M, s_m[i]);
    float Zt = 0.f;
    #pragma unroll
    for (int i = 0; i < 8; i++) Zt += s_z[i] * __expf(s_m[i] - M);
    float f = __expf(m - M) / Zt;

    float* ctx = g_rnn + b * KG;
    #pragma unroll
    for (int i = 0; i < 16; i++) {
        int c = 4 * (lane + 32 * i);
        atomicAdd(&ctx[c + 0], acc[i].x * f);
        atomicAdd(&ctx[c + 1], acc[i].y * f);
        atomicAdd(&ctx[c + 2], acc[i].z * f);
        atomicAdd(&ctx[c + 3], acc[i].w * f);
    }
}

// ---------------------------------------------------------------------------
// bf16x3 split GEMM:  C[128, N] (+)= A[128, K] @ B[N, K]^T  (fp32 in/out)
// B is piecewise over K (W_ih then W_hh for the gate GEMM).
// CTA tile 128x128, K-chunk 32, 8 warps (2x4), warp tile 64x32,
// mma.sync m16n8k16 bf16, fp32->bf16 hi/lo split on the fly.
// ---------------------------------------------------------------------------
__device__ __forceinline__ void ldm_x4(uint32_t* r, const __nv_bfloat16* p) {
    uint32_t a = (uint32_t)__cvta_generic_to_shared(p);
    asm volatile("ldmatrix.sync.aligned.m8n8.x4.shared.b16 {%0,%1,%2,%3}, [%4];\n"
                 : "=r"(r[0]), "=r"(r[1]), "=r"(r[2]), "=r"(r[3]) : "r"(a));
}
__device__ __forceinline__ void ldm_x2(uint32_t* r, const __nv_bfloat16* p) {
    uint32_t a = (uint32_t)__cvta_generic_to_shared(p);
    asm volatile("ldmatrix.sync.aligned.m8n8.x2.shared.b16 {%0,%1}, [%2];\n"
                 : "=r"(r[0]), "=r"(r[1]) : "r"(a));
}
__device__ __forceinline__ void mma_bf16(float* d, const uint32_t* a, const uint32_t* b) {
    asm volatile("mma.sync.aligned.m16n8k16.row.col.f32.bf16.bf16.f32 "
                 "{%0,%1,%2,%3}, {%4,%5,%6,%7}, {%8,%9}, {%0,%1,%2,%3};\n"
                 : "+f"(d[0]), "+f"(d[1]), "+f"(d[2]), "+f"(d[3])
                 : "r"(a[0]), "r"(a[1]), "r"(a[2]), "r"(a[3]), "r"(b[0]), "r"(b[1]));
}

__global__ __launch_bounds__(256) void gemm_kernel(
    int mode,  // 0 = gates (atomic, piecewise B), 1 = fc (store + bias)
    const float* __restrict__ W_ih, const float* __restrict__ W_hh,
    const float* __restrict__ W_fc, const float* __restrict__ b_fc,
    const float* __restrict__ h_new, float* __restrict__ pred)
{
    __shared__ __nv_bfloat16 sAh[128 * LDS_PAD], sAl[128 * LDS_PAD];
    __shared__ __nv_bfloat16 sBh[128 * LDS_PAD], sBl[128 * LDS_PAD];

    const float *A, *B1, *B2, *bias;
    float* C;
    int lda, k1, ldb1, ldb2, ldc, Ktot;
    if (mode == 0) {
        A = g_rnn;  lda = KG;  Ktot = KG;
        B1 = W_ih;  k1 = H2 + EMB;  ldb1 = H2 + EMB;
        B2 = W_hh;  ldb2 = HID;
        C = g_gates; ldc = NG; bias = nullptr;
    } else {
        A = h_new;  lda = HID; Ktot = HID;
        B1 = W_fc;  k1 = HID;  ldb1 = HID;
        B2 = W_fc;  ldb2 = HID;
        C = pred;   ldc = VOCAB; bias = b_fc;
    }

    int t = threadIdx.x, warp = t >> 5, lane = t & 31;
    int ntile = blockIdx.x;
    int nch = Ktot >> 5;
    int per = nch / gridDim.y;
    int c0 = blockIdx.y * per, c1 = c0 + per;

    float acc[4][4][4];
    #pragma unroll
    for (int mi = 0; mi < 4; mi++)
        #pragma unroll
        for (int ni = 0; ni < 4; ni++)
            #pragma unroll
            for (int q = 0; q < 4; q++) acc[mi][ni][q] = 0.f;

    int rowL[4], kqL[4];
    #pragma unroll
    for (int j = 0; j < 4; j++) { int idx = t + j * 256; rowL[j] = idx >> 3; kqL[j] = idx & 7; }

    float4 pa[4], pb[4];

    // prefetch chunk c0
    #pragma unroll
    for (int j = 0; j < 4; j++) {
        int k = (c0 << 5) + kqL[j] * 4;
        pa[j] = *(const float4*)(A + (size_t)rowL[j] * lda + k);
        int rg = ntile * 128 + rowL[j];
        const float* s = (k < k1) ? (B1 + (size_t)rg * ldb1 + k)
                                  : (B2 + (size_t)rg * ldb2 + (k - k1));
        pb[j] = *(const float4*)s;
    }

    int mw = (warp >> 2) * 64, nw = (warp & 3) * 32;

    for (int ch = c0; ch < c1; ++ch) {
        __syncthreads();
        // convert + store staged chunk (fp32 -> bf16 hi/lo)
        #pragma unroll
        for (int j = 0; j < 4; j++) {
            int off = rowL[j] * LDS_PAD + kqL[j] * 4;
            float av[4] = { pa[j].x, pa[j].y, pa[j].z, pa[j].w };
            float bv[4] = { pb[j].x, pb[j].y, pb[j].z, pb[j].w };
            #pragma unroll
            for (int c = 0; c < 4; c++) {
                __nv_bfloat16 h = __float2bfloat16(av[c]);
                sAh[off + c] = h;
                sAl[off + c] = __float2bfloat16(av[c] - __bfloat162float(h));
                h = __float2bfloat16(bv[c]);
                sBh[off + c] = h;
                sBl[off + c] = __float2bfloat16(bv[c] - __bfloat162float(h));
            }
        }
        __syncthreads();

        // issue next chunk's global loads (overlap with compute)
        if (ch + 1 < c1) {
            #pragma unroll
            for (int j = 0; j < 4; j++) {
                int k = ((ch + 1) << 5) + kqL[j] * 4;
                pa[j] = *(const float4*)(A + (size_t)rowL[j] * lda + k);
                int rg = ntile * 128 + rowL[j];
                const float* s = (k < k1) ? (B1 + (size_t)rg * ldb1 + k)
                                          : (B2 + (size_t)rg * ldb2 + (k - k1));
                pb[j] = *(const float4*)s;
            }
        }

        // compute on smem chunk: 2 k16 steps x (hi*hi + lo*hi + hi*lo)
        #pragma unroll
        for (int ks = 0; ks < 2; ks++) {
            uint32_t ah[4][4], al[4][4], bh[4][2], bl[4][2];
            int ar = mw + (lane & 15);
            int ac = ks * 16 + ((lane >> 4) << 3);
            #pragma unroll
            for (int mi = 0; mi < 4; mi++) {
                ldm_x4(ah[mi], &sAh[(ar + mi * 16) * LDS_PAD + ac]);
                ldm_x4(al[mi], &sAl[(ar + mi * 16) * LDS_PAD + ac]);
            }
            int br = nw + (lane & 7);
            int bc = ks * 16 + ((lane >> 3) & 1) * 8;
            #pragma unroll
            for (int ni = 0; ni < 4; ni++) {
                ldm_x2(bh[ni], &sBh[(br + ni * 8) * LDS_PAD + bc]);
                ldm_x2(bl[ni], &sBl[(br + ni * 8) * LDS_PAD + bc]);
            }
            #pragma unroll
            for (int mi = 0; mi < 4; mi++)
                #pragma unroll
                for (int ni = 0; ni < 4; ni++) mma_bf16(acc[mi][ni], ah[mi], bh[ni]);
            #pragma unroll
            for (int mi = 0; mi < 4; mi++)
                #pragma unroll
                for (int ni = 0; ni < 4; ni++) mma_bf16(acc[mi][ni], al[mi], bh[ni]);
            #pragma unroll
            for (int mi = 0; mi < 4; mi++)
                #pragma unroll
                for (int ni = 0; ni < 4; ni++) mma_bf16(acc[mi][ni], ah[mi], bl[ni]);
        }
    }

    // epilogue
    int r0 = mw + (lane >> 2);
    int cb = nw + (lane & 3) * 2;
    #pragma unroll
    for (int mi = 0; mi < 4; mi++) {
        #pragma unroll
        for (int ni = 0; ni < 4; ni++) {
            int ng0 = ntile * 128 + cb + ni * 8;
            int rA  = r0 + mi * 16;
            if (mode == 0) {
                atomicAdd(&C[(size_t)rA * ldc + ng0],           acc[mi][ni][0]);
                atomicAdd(&C[(size_t)rA * ldc + ng0 + 1],       acc[mi][ni][1]);
                atomicAdd(&C[(size_t)(rA + 8) * ldc + ng0],     acc[mi][ni][2]);
                atomicAdd(&C[(size_t)(rA + 8) * ldc + ng0 + 1], acc[mi][ni][3]);
            } else {
                C[(size_t)rA * ldc + ng0]           = acc[mi][ni][0] + bias[ng0];
                C[(size_t)rA * ldc + ng0 + 1]       = acc[mi][ni][1] + bias[ng0 + 1];
                C[(size_t)(rA + 8) * ldc + ng0]     = acc[mi][ni][2] + bias[ng0];
                C[(size_t)(rA + 8) * ldc + ng0 + 1] = acc[mi][ni][3] + bias[ng0 + 1];
            }
        }
    }
}

// ---------------------------------------------------------------------------
// LSTM pointwise: gates -> h_new, c_new (written straight into d_out)
// ---------------------------------------------------------------------------
__device__ __forceinline__ float sigmf(float x) { return 1.f / (1.f + __expf(-x)); }

__global__ void lstm_kernel(const float* __restrict__ b_ih,
                            const float* __restrict__ b_hh,
                            const float* __restrict__ cell,
                            float* __restrict__ h_out,
                            float* __restrict__ c_out)
{
    int b = blockIdx.x;
    const float* g = g_gates + b * NG;
    for (int j = threadIdx.x; j < HID; j += blockDim.x) {
        float ig = sigmf(g[j]            + b_ih[j]            + b_hh[j]);
        float fg = sigmf(g[HID + j]      + b_ih[HID + j]      + b_hh[HID + j]);
        float gg = tanhf(g[2 * HID + j]  + b_ih[2 * HID + j]  + b_hh[2 * HID + j]);
        float og = sigmf(g[3 * HID + j]  + b_ih[3 * HID + j]  + b_hh[3 * HID + j]);
        float c = fg * cell[b * HID + j] + ig * gg;
        float h = og * tanhf(c);
        c_out[b * HID + j] = c;
        h_out[b * HID + j] = h;
    }
}

// ---------------------------------------------------------------------------
extern "C" void kernel_launch(void* const* d_in, const int* in_sizes, int n_in,
                              void* d_out, int out_size)
{
    const int*   x      = (const int*)d_in[0];
    const float* enc    = (const float*)d_in[1];
    const float* hidden = (const float*)d_in[2];
    const float* cell   = (const float*)d_in[3];
    const float* emb    = (const float*)d_in[4];
    const float* W_e    = (const float*)d_in[5];
    const float* b_e    = (const float*)d_in[6];
    const float* W_ih   = (const float*)d_in[7];
    const float* W_hh   = (const float*)d_in[8];
    const float* b_ih   = (const float*)d_in[9];
    const float* b_hh   = (const float*)d_in[10];
    const float* W_fc   = (const float*)d_in[11];
    const float* b_fc   = (const float*)d_in[12];

    float* out   = (float*)d_out;
    float* h_out = out + (size_t)BATCH * VOCAB;
    float* c_out = h_out + BATCH * HID;

    prep_kernel<<<BATCH, 256>>>(x, emb, hidden);
    attn_kernel<<<BATCH, 256>>>(enc, hidden, W_e, b_e);
    gemm_kernel<<<dim3(NG / 128, 4), 256>>>(0, W_ih, W_hh, W_fc, b_fc, h_out, out);
    lstm_kernel<<<BATCH, 256>>>(b_ih, b_hh, cell, h_out, c_out);
    gemm_kernel<<<dim3(VOCAB / 128, 1), 256>>>(1, W_ih, W_hh, W_fc, b_fc, h_out, out);
}